// round 2
// baseline (speedup 1.0000x reference)
#include <cuda_runtime.h>
#include <cstdint>
#include <cstdio>

#define Bsz 128
#define Tsz 1024
#define Dsz 256
#define Hsz 256
#define WPAD 260   // 260 % 32 == 4 -> conflict-free LDS.128 phases, 16B aligned rows

// Scratch for x_proj = obs @ Wi + bi  : [B*T, 768] fp32
__device__ float g_xproj[(size_t)Bsz * Tsz * 3 * Hsz];
// done dtype mode: 0 = int32 per element, 1 = uint8 per element
__device__ int g_done_mode;

// ---------------------------------------------------------------------------
// Kernel 0: detect done dtype. Words of an int32 bool array are all 0/1.
// If the buffer is byte-packed bools, many 4-byte words exceed 1.
// Deterministic for fixed input data.
// ---------------------------------------------------------------------------
__global__ void detect_done_kernel(const unsigned int* __restrict__ done_words)
{
    __shared__ int found;
    if (threadIdx.x == 0) found = 0;
    __syncthreads();
    // 32768 words are valid under both interpretations (131072 bytes min)
    for (int i = threadIdx.x; i < 32768; i += blockDim.x) {
        if (done_words[i] > 1u) { found = 1; break; }
    }
    __syncthreads();
    if (threadIdx.x == 0) g_done_mode = found;
}

// ---------------------------------------------------------------------------
// Kernel 1: x_proj SGEMM  (M=131072, N=768, K=256), 128x128 tiles, BK=8
// ---------------------------------------------------------------------------
__global__ void __launch_bounds__(256) xproj_kernel(const float* __restrict__ obs,
                                                    const float* __restrict__ Wi,
                                                    const float* __restrict__ bi)
{
    __shared__ float As[8][128];
    __shared__ float Bs[8][128];

    const int bM = blockIdx.y * 128;
    const int bN = blockIdx.x * 128;
    const int tid = threadIdx.x;
    const int tx = tid & 15;         // 0..15 -> N
    const int ty = tid >> 4;         // 0..15 -> M
    const int cRow = ty * 8;
    const int cCol = tx * 8;

    const int arow = tid >> 1;           // 0..127
    const int acol = (tid & 1) * 4;      // 0 or 4
    const int brow = tid >> 5;           // 0..7
    const int bcol = (tid & 31) * 4;     // 0..124

    const float* aptr = obs + (size_t)(bM + arow) * Dsz + acol;
    const float* bptr = Wi + (size_t)brow * 768 + bN + bcol;

    float acc[8][8];
#pragma unroll
    for (int i = 0; i < 8; i++)
#pragma unroll
        for (int j = 0; j < 8; j++) acc[i][j] = 0.f;

    for (int k0 = 0; k0 < Dsz; k0 += 8) {
        float4 av = *(const float4*)(aptr + k0);
        As[acol + 0][arow] = av.x;
        As[acol + 1][arow] = av.y;
        As[acol + 2][arow] = av.z;
        As[acol + 3][arow] = av.w;
        float4 bv = *(const float4*)(bptr + (size_t)k0 * 768);
        *(float4*)&Bs[brow][bcol] = bv;
        __syncthreads();

#pragma unroll
        for (int k = 0; k < 8; k++) {
            float ra[8], rb[8];
            *(float4*)(ra)     = *(const float4*)&As[k][cRow];
            *(float4*)(ra + 4) = *(const float4*)&As[k][cRow + 4];
            *(float4*)(rb)     = *(const float4*)&Bs[k][cCol];
            *(float4*)(rb + 4) = *(const float4*)&Bs[k][cCol + 4];
#pragma unroll
            for (int i = 0; i < 8; i++)
#pragma unroll
                for (int j = 0; j < 8; j++)
                    acc[i][j] = fmaf(ra[i], rb[j], acc[i][j]);
        }
        __syncthreads();
    }

    float4 b0 = *(const float4*)(bi + bN + cCol);
    float4 b1 = *(const float4*)(bi + bN + cCol + 4);
#pragma unroll
    for (int i = 0; i < 8; i++) {
        float* orow = g_xproj + (size_t)(bM + cRow + i) * 768 + bN + cCol;
        float4 o0 = make_float4(acc[i][0] + b0.x, acc[i][1] + b0.y,
                                acc[i][2] + b0.z, acc[i][3] + b0.w);
        float4 o1 = make_float4(acc[i][4] + b1.x, acc[i][5] + b1.y,
                                acc[i][6] + b1.z, acc[i][7] + b1.w);
        *(float4*)(orow)     = o0;
        *(float4*)(orow + 4) = o1;
    }
}

// ---------------------------------------------------------------------------
// Kernel 2: GRU scan. 32 clusters x 4 CTAs. Cluster c owns batches [4c,4c+4).
// CTA rank owns H-columns [rank*64, rank*64+64): weight slice (192 cols) in SMEM.
// h exchanged via st.shared::cluster + barrier.cluster per step.
// ---------------------------------------------------------------------------
__device__ __forceinline__ float fsigmoid(float x) {
    return __fdividef(1.f, 1.f + __expf(-x));
}
__device__ __forceinline__ float ftanh(float x) {
    return __fdividef(2.f, 1.f + __expf(-2.f * x)) - 1.f;
}

extern __shared__ float smem[];

__global__ void __launch_bounds__(256, 1) __cluster_dims__(4, 1, 1)
scan_kernel(const void* __restrict__ done_raw,
            const float* __restrict__ init_h,
            const float* __restrict__ Wh_rz,
            const float* __restrict__ Wh_n,
            const float* __restrict__ bh_n,
            float* __restrict__ out)
{
    // SMEM layout (floats):
    float* W_s   = smem;                       // [192][WPAD]
    float* hbuf  = W_s + 192 * WPAD;           // [2][4][256]
    float* xs    = hbuf + 2 * 4 * 256;         // [4][192]
    float* accs  = xs + 4 * 192;               // [192][4]
    float* bhn_s = accs + 192 * 4;             // [64]
    int*   done_s = (int*)(bhn_s + 64);        // [4]

    const int tid  = threadIdx.x;
    const int rank = blockIdx.x & 3;
    const int cl   = blockIdx.x >> 2;
    const int b0   = cl * 4;

    const int done_mode = g_done_mode;   // 0: int32, 1: uint8
    const int* done_i32 = (const int*)done_raw;
    const unsigned char* done_u8 = (const unsigned char*)done_raw;

    // --- load weight slice (transposed into [col][k], pad WPAD) ---
    for (int idx = tid; idx < 192 * 256; idx += 256) {
        int k = idx / 192;
        int c = idx - k * 192;
        float v;
        if (c < 128) {
            int scol = (c < 64) ? (rank * 64 + c) : (256 + rank * 64 + (c - 64));
            v = Wh_rz[(size_t)k * 512 + scol];
        } else {
            v = Wh_n[(size_t)k * 256 + rank * 64 + (c - 128)];
        }
        W_s[c * WPAD + k] = v;
    }
    if (tid < 64) bhn_s[tid] = bh_n[rank * 64 + tid];

    // --- init h (local copy of all 4 batches' full h) ---
    for (int idx = tid; idx < 4 * 256; idx += 256)
        hbuf[idx] = init_h[(size_t)(b0 + (idx >> 8)) * Hsz + (idx & 255)];
    __syncthreads();

    uint32_t hbuf_u32;
    {
        asm("{ .reg .u64 t; cvta.to.shared.u64 t, %1; cvt.u32.u64 %0, t; }"
            : "=r"(hbuf_u32) : "l"(hbuf));
    }

    float* ys = out + Bsz * Hsz;
    int p = 0;

    for (int t = 0; t < Tsz; t++) {
        if (tid < 192) {
            // dot products: 192 columns x 4 batches, K=256
            const float4* Wc = (const float4*)(W_s + tid * WPAD);
            const float4* hb = (const float4*)(hbuf + p * 1024);
            float a0 = 0.f, a1 = 0.f, a2 = 0.f, a3 = 0.f;
#pragma unroll 4
            for (int kq = 0; kq < 64; kq++) {
                float4 w  = Wc[kq];
                float4 h0 = hb[kq];
                float4 h1 = hb[64 + kq];
                float4 h2 = hb[128 + kq];
                float4 h3 = hb[192 + kq];
                a0 = fmaf(w.x, h0.x, fmaf(w.y, h0.y, fmaf(w.z, h0.z, fmaf(w.w, h0.w, a0))));
                a1 = fmaf(w.x, h1.x, fmaf(w.y, h1.y, fmaf(w.z, h1.z, fmaf(w.w, h1.w, a1))));
                a2 = fmaf(w.x, h2.x, fmaf(w.y, h2.y, fmaf(w.z, h2.z, fmaf(w.w, h2.w, a2))));
                a3 = fmaf(w.x, h3.x, fmaf(w.y, h3.y, fmaf(w.z, h3.z, fmaf(w.w, h3.w, a3))));
            }
            ((float4*)accs)[tid] = make_float4(a0, a1, a2, a3);
        } else {
            // prefetch x_proj slice + done flags for this step
            int lt = tid - 192;
            if (lt < 4) {
                size_t di = (size_t)(b0 + lt) * Tsz + t;
                done_s[lt] = done_mode ? (int)done_u8[di] : done_i32[di];
            }
            for (int i = lt; i < 768; i += 64) {
                int g = i / 192;
                int c = i - g * 192;
                int col = (c < 64) ? (rank * 64 + c)
                        : (c < 128) ? (256 + rank * 64 + (c - 64))
                                    : (512 + rank * 64 + (c - 128));
                xs[g * 192 + c] = g_xproj[((size_t)(b0 + g) * Tsz + t) * 768 + col];
            }
        }
        __syncthreads();

        {
            const int g  = tid >> 6;
            const int j  = tid & 63;
            const int jg = rank * 64 + j;
            float hr = accs[j * 4 + g];
            float hz = accs[(64 + j) * 4 + g];
            float hn = accs[(128 + j) * 4 + g];
            float hcur = hbuf[p * 1024 + g * 256 + jg];
            if (done_s[g]) { hr = 0.f; hz = 0.f; hn = 0.f; hcur = 0.f; }
            float r = fsigmoid(xs[g * 192 + j] + hr);
            float z = fsigmoid(xs[g * 192 + 64 + j] + hz);
            float n = ftanh(xs[g * 192 + 128 + j] + r * (hn + bhn_s[j]));
            float hnew = n + z * (hcur - n);

            ys[((size_t)(b0 + g) * Tsz + t) * Hsz + jg] = hnew;
            if (t == Tsz - 1) out[(b0 + g) * Hsz + jg] = hnew;

            // broadcast h_new to all 4 cluster CTAs' next-phase buffer
            uint32_t la = hbuf_u32 + (uint32_t)(((1 - p) * 1024 + g * 256 + jg) * 4);
#pragma unroll
            for (uint32_t dst = 0; dst < 4; dst++) {
                uint32_t ra;
                asm volatile("mapa.shared::cluster.u32 %0, %1, %2;"
                             : "=r"(ra) : "r"(la), "r"(dst));
                asm volatile("st.shared::cluster.f32 [%0], %1;"
                             :: "r"(ra), "f"(hnew) : "memory");
            }
        }

        asm volatile("barrier.cluster.arrive.aligned;" ::: "memory");
        asm volatile("barrier.cluster.wait.aligned;" ::: "memory");
        p ^= 1;
    }
}

// ---------------------------------------------------------------------------
// Launch
// ---------------------------------------------------------------------------
static const int SCAN_SMEM_BYTES =
    (192 * WPAD + 2 * 4 * 256 + 4 * 192 + 192 * 4 + 64 + 4) * 4;

extern "C" void kernel_launch(void* const* d_in, const int* in_sizes, int n_in,
                              void* d_out, int out_size)
{
    (void)in_sizes; (void)n_in; (void)out_size;
    const float* obs    = (const float*)d_in[0];
    const void*  done   = d_in[1];
    const float* init_h = (const float*)d_in[2];
    const float* Wi     = (const float*)d_in[3];
    const float* bi     = (const float*)d_in[4];
    const float* Wh_rz  = (const float*)d_in[5];
    const float* Wh_n   = (const float*)d_in[6];
    const float* bh_n   = (const float*)d_in[7];
    float* out = (float*)d_out;

    cudaFuncSetAttribute(scan_kernel, cudaFuncAttributeMaxDynamicSharedMemorySize,
                         SCAN_SMEM_BYTES);

    detect_done_kernel<<<1, 256>>>((const unsigned int*)done);

    dim3 ggrid(768 / 128, (Bsz * Tsz) / 128);  // (6, 1024)
    xproj_kernel<<<ggrid, 256>>>(obs, Wi, bi);

    scan_kernel<<<128, 256, SCAN_SMEM_BYTES>>>(done, init_h, Wh_rz, Wh_n, bh_n, out);
}